// round 6
// baseline (speedup 1.0000x reference)
#include <cuda_runtime.h>
#include <cuda_fp16.h>
#include <cstdint>

// Problem constants
#define BATCH 4
#define SEQ   2048
#define CDIM  1024
#define NHEAD 16
#define HDIM  64
#define MROWS (BATCH*SEQ)          // 8192
#define QKVN  (3*CDIM)             // 3072

// fp16 scratch
__device__ __half g_xh  [(size_t)MROWS * CDIM];
__device__ __half g_wat [(size_t)QKVN * CDIM];   // W_attn^T [N,K]
__device__ __half g_wpt [(size_t)CDIM * CDIM];   // W_proj^T [N,K]
__device__ __half g_qkvh[(size_t)MROWS * QKVN];
__device__ __half g_yh  [(size_t)MROWS * CDIM];

// ---------------------------------------------------------------------------
__device__ __forceinline__ uint32_t smem_u32(const void* p) {
    uint32_t a;
    asm("{ .reg .u64 t; cvta.to.shared.u64 t, %1; cvt.u32.u64 %0, t; }" : "=r"(a) : "l"(p));
    return a;
}
__device__ __forceinline__ void cp16(uint32_t s, const void* g) {
    asm volatile("cp.async.cg.shared.global [%0], [%1], 16;" :: "r"(s), "l"(g));
}
#define CP_COMMIT() asm volatile("cp.async.commit_group;")
#define CP_WAIT(n)  asm volatile("cp.async.wait_group %0;" :: "n"(n))

#define LDSM_X4(r0,r1,r2,r3,addr) \
    asm volatile("ldmatrix.sync.aligned.m8n8.x4.shared.b16 {%0,%1,%2,%3},[%4];" \
        : "=r"(r0),"=r"(r1),"=r"(r2),"=r"(r3) : "r"(addr))
#define LDSM_X4_T(r0,r1,r2,r3,addr) \
    asm volatile("ldmatrix.sync.aligned.m8n8.x4.trans.shared.b16 {%0,%1,%2,%3},[%4];" \
        : "=r"(r0),"=r"(r1),"=r"(r2),"=r"(r3) : "r"(addr))

__device__ __forceinline__ void mma_f16(
    float& c0, float& c1, float& c2, float& c3,
    uint32_t a0, uint32_t a1, uint32_t a2, uint32_t a3,
    uint32_t b0, uint32_t b1)
{
    asm volatile(
        "mma.sync.aligned.m16n8k16.row.col.f32.f16.f16.f32 "
        "{%0,%1,%2,%3}, {%4,%5,%6,%7}, {%8,%9}, {%0,%1,%2,%3};"
        : "+f"(c0), "+f"(c1), "+f"(c2), "+f"(c3)
        : "r"(a0), "r"(a1), "r"(a2), "r"(a3), "r"(b0), "r"(b1));
}
__device__ __forceinline__ uint32_t pack_h2(float a, float b) {
    __half2 h = __floats2half2_rn(a, b);
    return *(uint32_t*)&h;
}

// ---------------------------------------------------------------------------
// fp32 -> fp16 convert
// ---------------------------------------------------------------------------
__global__ void f2h_kernel(const float4* __restrict__ in, uint2* __restrict__ out, int n4) {
    int i = blockIdx.x * 256 + threadIdx.x;
    if (i < n4) {
        float4 v = in[i];
        out[i] = make_uint2(pack_h2(v.x, v.y), pack_h2(v.z, v.w));
    }
}

// fp32 W[K,N] -> fp16 WT[N,K]
__global__ void transpose_h(const float* __restrict__ W, __half* __restrict__ WT,
                            int K, int N) {
    __shared__ float tile[32][33];
    int n0 = blockIdx.x * 32, k0 = blockIdx.y * 32;
    int tx = threadIdx.x, ty = threadIdx.y;
#pragma unroll
    for (int i = 0; i < 4; i++)
        tile[ty + 8 * i][tx] = W[(size_t)(k0 + ty + 8 * i) * N + n0 + tx];
    __syncthreads();
#pragma unroll
    for (int i = 0; i < 4; i++)
        WT[(size_t)(n0 + ty + 8 * i) * K + k0 + tx] = __float2half(tile[tx][ty + 8 * i]);
}

// ---------------------------------------------------------------------------
// fp16 GEMM v2: C[M,N] = A[M,K] @ BT[N,K]^T + bias[N]
// Block 128x256, warp tile 64x64 (8 warps 2x4), BK=32, 4-stage cp.async.
// A, BT both K-major fp16. Smem A: [m][k] stride 40; B: [n][k] stride 40.
// ---------------------------------------------------------------------------
#define BM 128
#define BN 256
#define GBK 32
#define NSTAGE 4
#define ASTR 40                        // halves per A row (32 + 8 pad)
#define BKSTR 40                       // halves per B row (32 + 8 pad)
#define A_ST_BYTES (BM * ASTR * 2)     // 10240
#define B_ST_BYTES (BN * BKSTR * 2)    // 20480
#define B_BASE     (NSTAGE * A_ST_BYTES)
#define SMEM_GEMM  (NSTAGE * (A_ST_BYTES + B_ST_BYTES))   // 122880

template<int WRITE_HALF>
__global__ __launch_bounds__(256) void hgemm_v2(
    const __half* __restrict__ A, const __half* __restrict__ BT,
    const float* __restrict__ bias, void* __restrict__ Cout,
    int M, int N, int K)
{
    extern __shared__ __align__(16) char sm[];
    const uint32_t smb = smem_u32(sm);

    const int tid  = threadIdx.x;
    const int w    = tid >> 5;
    const int lane = tid & 31;
    const int g    = lane >> 2;
    const int tig  = lane & 3;
    const int brow = blockIdx.x * BM;
    const int bcol = blockIdx.y * BN;
    const int wr   = (w >> 2) * 64;    // warp m base: 0 / 64
    const int wc   = (w & 3) * 64;     // warp n base: 0..192

    // ldmatrix per-thread offsets (bytes)
    const uint32_t a_off = 2 * ((wr + (lane & 15)) * ASTR + (lane >> 4) * 8);
    const uint32_t b_off = 2 * ((wc + (lane & 15)) * BKSTR + (lane >> 4) * 8);

    float acc[4][8][4];
#pragma unroll
    for (int i = 0; i < 4; i++)
#pragma unroll
        for (int j = 0; j < 8; j++)
#pragma unroll
            for (int f = 0; f < 4; f++) acc[i][j][f] = 0.f;

    auto load_chunk = [&](int s, int k0) {
#pragma unroll
        for (int l = 0; l < 2; l++) {          // A: 128 rows x 4 chunks of 8
            int idx = tid + l * 256;
            int m = idx >> 2, c = idx & 3;
            cp16(smb + s * A_ST_BYTES + 2 * (m * ASTR + c * 8),
                 A + (size_t)(brow + m) * K + k0 + c * 8);
        }
#pragma unroll
        for (int l = 0; l < 4; l++) {          // B: 256 rows x 4 chunks of 8
            int idx = tid + l * 256;
            int n = idx >> 2, c = idx & 3;
            cp16(smb + B_BASE + s * B_ST_BYTES + 2 * (n * BKSTR + c * 8),
                 BT + (size_t)(bcol + n) * K + k0 + c * 8);
        }
        CP_COMMIT();
    };

    const int KT = K / GBK;     // 32
    load_chunk(0, 0);
    load_chunk(1, GBK);
    load_chunk(2, 2 * GBK);

    for (int t = 0; t < KT; t++) {
        const int cur = t & (NSTAGE - 1);
        CP_WAIT(2);
        __syncthreads();

        const uint32_t as_s = smb + cur * A_ST_BYTES;
        const uint32_t bs_s = smb + B_BASE + cur * B_ST_BYTES;
#pragma unroll
        for (int ks = 0; ks < 32; ks += 16) {
            uint32_t af[4][4];
#pragma unroll
            for (int i = 0; i < 4; i++)
                LDSM_X4(af[i][0], af[i][1], af[i][2], af[i][3],
                        as_s + a_off + 2 * (i * 16 * ASTR + ks));
            uint32_t bf[8][2];
#pragma unroll
            for (int jp = 0; jp < 4; jp++) {
                uint32_t t0, t1, t2, t3;
                LDSM_X4(t0, t1, t2, t3,
                        bs_s + b_off + 2 * (jp * 16 * BKSTR + ks));
                bf[2*jp][0]   = t0; bf[2*jp][1]   = t2;
                bf[2*jp+1][0] = t1; bf[2*jp+1][1] = t3;
            }
#pragma unroll
            for (int i = 0; i < 4; i++)
#pragma unroll
                for (int j = 0; j < 8; j++)
                    mma_f16(acc[i][j][0], acc[i][j][1], acc[i][j][2], acc[i][j][3],
                            af[i][0], af[i][1], af[i][2], af[i][3],
                            bf[j][0], bf[j][1]);
        }
        __syncthreads();
        if (t + 3 < KT) load_chunk((t + 3) & (NSTAGE - 1), (t + 3) * GBK);
    }

    // Epilogue
#pragma unroll
    for (int i = 0; i < 4; i++) {
#pragma unroll
        for (int j = 0; j < 8; j++) {
            int row = brow + wr + i * 16 + g;
            int col = bcol + wc + j * 8 + 2 * tig;
            float b0 = bias[col], b1 = bias[col + 1];
            if (WRITE_HALF) {
                __half* Ch = (__half*)Cout;
                *(uint32_t*)&Ch[(size_t)row * N + col] =
                    pack_h2(acc[i][j][0] + b0, acc[i][j][1] + b1);
                *(uint32_t*)&Ch[(size_t)(row + 8) * N + col] =
                    pack_h2(acc[i][j][2] + b0, acc[i][j][3] + b1);
            } else {
                float* Cf = (float*)Cout;
                *(float2*)&Cf[(size_t)row * N + col] =
                    make_float2(acc[i][j][0] + b0, acc[i][j][1] + b1);
                *(float2*)&Cf[(size_t)(row + 8) * N + col] =
                    make_float2(acc[i][j][2] + b0, acc[i][j][3] + b1);
            }
        }
    }
}

// ---------------------------------------------------------------------------
// Causal flash attention, fp16 HMMA + ldmatrix, cp.async double-buffered K/V.
// Grid (T/128, H, B), 256 threads (8 warps x 16 q-rows = BQ 128), BKV=64.
// ---------------------------------------------------------------------------
#define QVSTR 72
#define Q_BYTES  (128 * QVSTR * 2)   // 18432
#define KV_BYTES (64 * QVSTR * 2)    // 9216
#define SM_K     Q_BYTES
#define SM_V     (SM_K + 2 * KV_BYTES)
#define SMEM_ATT (SM_V + 2 * KV_BYTES)   // 55296

__global__ __launch_bounds__(256) void attn_h_kernel(
    const __half* __restrict__ qkv, __half* __restrict__ y)
{
    extern __shared__ __align__(16) char sma[];
    const uint32_t qs_u = smem_u32(sma);
    const uint32_t ks_u = qs_u + SM_K;
    const uint32_t vs_u = qs_u + SM_V;
    __half* Qs = (__half*)sma;

    const int qb = blockIdx.x;
    const int h  = blockIdx.y;
    const int b  = blockIdx.z;
    const int tid  = threadIdx.x;
    const int w    = tid >> 5;
    const int lane = tid & 31;
    const int g    = lane >> 2;
    const int tig  = lane & 3;

    const uint32_t qa_off = 2 * ((w * 16 + (lane & 15)) * QVSTR + (lane >> 4) * 8);
    const uint32_t kb_off = 2 * (((lane & 7) + ((lane >> 4) ? 8 : 0)) * QVSTR + ((lane & 8) ? 8 : 0));
    const uint32_t vb_off = 2 * (((lane & 7) + (lane & 8)) * QVSTR + ((lane >> 4) ? 8 : 0));

    const __half* base = qkv + (size_t)(b * SEQ) * QKVN + h * HDIM;
    const int q0 = qb * 128;

    auto load_kv = [&](int s, int kt) {
#pragma unroll
        for (int l = 0; l < 2; l++) {
            int idx = tid + l * 256;
            int r = idx >> 3, c8 = (idx & 7) * 8;
            size_t ro = (size_t)(kt * 64 + r) * QKVN + c8;
            uint32_t so = s * KV_BYTES + 2 * (r * QVSTR + c8);
            cp16(ks_u + so, base + CDIM + ro);
            cp16(vs_u + so, base + 2 * CDIM + ro);
        }
        CP_COMMIT();
    };

    // Load Q tile (scaled by 1/8 = 1/sqrt(64); exact in fp16)
    const __half2 sc = __floats2half2_rn(0.125f, 0.125f);
#pragma unroll
    for (int l = 0; l < 4; l++) {
        int idx = tid + l * 256;
        int r = idx >> 3, c8 = (idx & 7) * 8;
        uint4 v = *(const uint4*)&base[(size_t)(q0 + r) * QKVN + c8];
        __half2* hv = (__half2*)&v;
        hv[0] = __hmul2(hv[0], sc); hv[1] = __hmul2(hv[1], sc);
        hv[2] = __hmul2(hv[2], sc); hv[3] = __hmul2(hv[3], sc);
        *(uint4*)&Qs[r * QVSTR + c8] = v;
    }

    float o[8][4];
#pragma unroll
    for (int j = 0; j < 8; j++)
#pragma unroll
        for (int f = 0; f < 4; f++) o[j][f] = 0.f;
    float m0 = -1e30f, m1 = -1e30f, l0 = 0.f, l1 = 0.f;

    const int last = 2 * qb + 1;
    load_kv(0, 0);

    for (int kt = 0; kt <= last; kt++) {
        const int bs = kt & 1;
        __syncthreads();
        if (kt < last) { load_kv(bs ^ 1, kt + 1); CP_WAIT(1); }
        else           { CP_WAIT(0); }
        __syncthreads();

        const uint32_t ksb = ks_u + bs * KV_BYTES;
        const uint32_t vsb = vs_u + bs * KV_BYTES;

        // S = Q K^T (warp rows 16, cols 64)
        float s[8][4];
#pragma unroll
        for (int j = 0; j < 8; j++)
#pragma unroll
            for (int f = 0; f < 4; f++) s[j][f] = 0.f;
#pragma unroll
        for (int ks = 0; ks < 64; ks += 16) {
            uint32_t a0, a1, a2, a3;
            LDSM_X4(a0, a1, a2, a3, qs_u + qa_off + 2 * ks);
#pragma unroll
            for (int jp = 0; jp < 4; jp++) {
                uint32_t b0, b1, b2, b3;
                LDSM_X4(b0, b1, b2, b3, ksb + kb_off + 2 * (jp * 16 * QVSTR + ks));
                mma_f16(s[2*jp][0], s[2*jp][1], s[2*jp][2], s[2*jp][3],
                        a0, a1, a2, a3, b0, b1);
                mma_f16(s[2*jp+1][0], s[2*jp+1][1], s[2*jp+1][2], s[2*jp+1][3],
                        a0, a1, a2, a3, b2, b3);
            }
        }

        // Causal mask (only tiles reaching this warp's diagonal need it)
        const int rl0 = q0 + w * 16 + g;
        if (kt * 64 + 63 > rl0) {
            const int r1g = rl0 + 8;
#pragma unroll
            for (int j = 0; j < 8; j++) {
                int c = kt * 64 + j * 8 + 2 * tig;
                if (c     > rl0) s[j][0] = -1e30f;
                if (c + 1 > rl0) s[j][1] = -1e30f;
                if (c     > r1g) s[j][2] = -1e30f;
                if (c + 1 > r1g) s[j][3] = -1e30f;
            }
        }

        // Online softmax
        float rm0 = -1e30f, rm1 = -1e30f;
#pragma unroll
        for (int j = 0; j < 8; j++) {
            rm0 = fmaxf(rm0, fmaxf(s[j][0], s[j][1]));
            rm1 = fmaxf(rm1, fmaxf(s[j][2], s[j][3]));
        }
#pragma unroll
        for (int off = 1; off < 4; off <<= 1) {
            rm0 = fmaxf(rm0, __shfl_xor_sync(0xffffffffu, rm0, off));
            rm1 = fmaxf(rm1, __shfl_xor_sync(0xffffffffu, rm1, off));
        }
        float mn0 = fmaxf(m0, rm0), mn1 = fmaxf(m1, rm1);
        float al0 = __expf(m0 - mn0), al1 = __expf(m1 - mn1);
        float ls0 = 0.f, ls1 = 0.f;
#pragma unroll
        for (int j = 0; j < 8; j++) {
            s[j][0] = __expf(s[j][0] - mn0);
            s[j][1] = __expf(s[j][1] - mn0);
            s[j][2] = __expf(s[j][2] - mn1);
            s[j][3] = __expf(s[j][3] - mn1);
            ls0 += s[j][0] + s[j][1];
            ls1 += s[j][2] + s[j][3];
        }
#pragma unroll
        for (int off = 1; off < 4; off <<= 1) {
            ls0 += __shfl_xor_sync(0xffffffffu, ls0, off);
            ls1 += __shfl_xor_sync(0xffffffffu, ls1, off);
        }
        l0 = l0 * al0 + ls0;
        l1 = l1 * al1 + ls1;
        m0 = mn0; m1 = mn1;
#pragma unroll
        for (int j = 0; j < 8; j++) {
            o[j][0] *= al0; o[j][1] *= al0;
            o[j][2] *= al1; o[j][3] *= al1;
        }

        // O += P @ V
#pragma unroll
        for (int ks2 = 0; ks2 < 4; ks2++) {
            uint32_t a0 = pack_h2(s[2*ks2][0],   s[2*ks2][1]);
            uint32_t a1 = pack_h2(s[2*ks2][2],   s[2*ks2][3]);
            uint32_t a2 = pack_h2(s[2*ks2+1][0], s[2*ks2+1][1]);
            uint32_t a3 = pack_h2(s[2*ks2+1][2], s[2*ks2+1][3]);
#pragma unroll
            for (int jp = 0; jp < 4; jp++) {
                uint32_t b0, b1, b2, b3;
                LDSM_X4_T(b0, b1, b2, b3,
                          vsb + vb_off + 2 * (ks2 * 16 * QVSTR + jp * 16));
                mma_f16(o[2*jp][0], o[2*jp][1], o[2*jp][2], o[2*jp][3],
                        a0, a1, a2, a3, b0, b1);
                mma_f16(o[2*jp+1][0], o[2*jp+1][1], o[2*jp+1][2], o[2*jp+1][3],
                        a0, a1, a2, a3, b2, b3);
            }
        }
    }

    float il0 = 1.0f / l0, il1 = 1.0f / l1;
    size_t r0 = (size_t)(b * SEQ + q0 + w * 16 + g) * CDIM + h * HDIM;
    size_t r1 = r0 + 8 * CDIM;
#pragma unroll
    for (int j = 0; j < 8; j++) {
        int c = j * 8 + 2 * tig;
        *(uint32_t*)&y[r0 + c] = pack_h2(o[j][0] * il0, o[j][1] * il0);
        *(uint32_t*)&y[r1 + c] = pack_h2(o[j][2] * il1, o[j][3] * il1);
    }
}

// ---------------------------------------------------------------------------
extern "C" void kernel_launch(void* const* d_in, const int* in_sizes, int n_in,
                              void* d_out, int out_size)
{
    const float* x      = (const float*)d_in[0];
    const float* W_attn = (const float*)d_in[1];
    const float* b_attn = (const float*)d_in[2];
    const float* W_proj = (const float*)d_in[3];
    const float* b_proj = (const float*)d_in[4];
    float* out = (float*)d_out;

    __half *xh, *wat, *wpt, *qkvh, *yh;
    cudaGetSymbolAddress((void**)&xh,   g_xh);
    cudaGetSymbolAddress((void**)&wat,  g_wat);
    cudaGetSymbolAddress((void**)&wpt,  g_wpt);
    cudaGetSymbolAddress((void**)&qkvh, g_qkvh);
    cudaGetSymbolAddress((void**)&yh,   g_yh);

    cudaFuncSetAttribute(hgemm_v2<1>, cudaFuncAttributeMaxDynamicSharedMemorySize, SMEM_GEMM);
    cudaFuncSetAttribute(hgemm_v2<0>, cudaFuncAttributeMaxDynamicSharedMemorySize, SMEM_GEMM);
    cudaFuncSetAttribute(attn_h_kernel, cudaFuncAttributeMaxDynamicSharedMemorySize, SMEM_ATT);

    // 0) fp16 conversions / weight transposes
    {
        int n4 = (MROWS * CDIM) / 4;
        f2h_kernel<<<(n4 + 255) / 256, 256>>>((const float4*)x, (uint2*)xh, n4);
        transpose_h<<<dim3(QKVN / 32, CDIM / 32), dim3(32, 8)>>>(W_attn, wat, CDIM, QKVN);
        transpose_h<<<dim3(CDIM / 32, CDIM / 32), dim3(32, 8)>>>(W_proj, wpt, CDIM, CDIM);
    }
    // 1) QKV projection (fp16 out)
    {
        dim3 grid(MROWS / BM, QKVN / BN);
        hgemm_v2<1><<<grid, 256, SMEM_GEMM>>>(xh, wat, b_attn, qkvh, MROWS, QKVN, CDIM);
    }
    // 2) Causal attention (fp16 out)
    {
        dim3 grid(SEQ / 128, NHEAD, BATCH);
        attn_h_kernel<<<grid, 256, SMEM_ATT>>>(qkvh, yh);
    }
    // 3) Output projection (fp32 out)
    {
        dim3 grid(MROWS / BM, CDIM / BN);
        hgemm_v2<0><<<grid, 256, SMEM_GEMM>>>(yh, wpt, b_proj, out, MROWS, CDIM, CDIM);
    }
}

// round 7
// speedup vs baseline: 1.1481x; 1.1481x over previous
#include <cuda_runtime.h>
#include <cuda_fp16.h>
#include <cstdint>

// Problem constants
#define BATCH 4
#define SEQ   2048
#define CDIM  1024
#define NHEAD 16
#define HDIM  64
#define MROWS (BATCH*SEQ)          // 8192
#define QKVN  (3*CDIM)             // 3072

// fp16 scratch
__device__ __half g_xh  [(size_t)MROWS * CDIM];
__device__ __half g_wat [(size_t)QKVN * CDIM];   // W_attn^T [N,K]
__device__ __half g_wpt [(size_t)CDIM * CDIM];   // W_proj^T [N,K]
__device__ __half g_qkvh[(size_t)MROWS * QKVN];
__device__ __half g_yh  [(size_t)MROWS * CDIM];

// ---------------------------------------------------------------------------
__device__ __forceinline__ uint32_t smem_u32(const void* p) {
    uint32_t a;
    asm("{ .reg .u64 t; cvta.to.shared.u64 t, %1; cvt.u32.u64 %0, t; }" : "=r"(a) : "l"(p));
    return a;
}
__device__ __forceinline__ void cp16(uint32_t s, const void* g) {
    asm volatile("cp.async.cg.shared.global [%0], [%1], 16;" :: "r"(s), "l"(g));
}
#define CP_COMMIT() asm volatile("cp.async.commit_group;")
#define CP_WAIT(n)  asm volatile("cp.async.wait_group %0;" :: "n"(n))

#define LDSM_X4(r0,r1,r2,r3,addr) \
    asm volatile("ldmatrix.sync.aligned.m8n8.x4.shared.b16 {%0,%1,%2,%3},[%4];" \
        : "=r"(r0),"=r"(r1),"=r"(r2),"=r"(r3) : "r"(addr))
#define LDSM_X4_T(r0,r1,r2,r3,addr) \
    asm volatile("ldmatrix.sync.aligned.m8n8.x4.trans.shared.b16 {%0,%1,%2,%3},[%4];" \
        : "=r"(r0),"=r"(r1),"=r"(r2),"=r"(r3) : "r"(addr))

__device__ __forceinline__ void mma_f16(
    float& c0, float& c1, float& c2, float& c3,
    uint32_t a0, uint32_t a1, uint32_t a2, uint32_t a3,
    uint32_t b0, uint32_t b1)
{
    asm volatile(
        "mma.sync.aligned.m16n8k16.row.col.f32.f16.f16.f32 "
        "{%0,%1,%2,%3}, {%4,%5,%6,%7}, {%8,%9}, {%0,%1,%2,%3};"
        : "+f"(c0), "+f"(c1), "+f"(c2), "+f"(c3)
        : "r"(a0), "r"(a1), "r"(a2), "r"(a3), "r"(b0), "r"(b1));
}
__device__ __forceinline__ uint32_t pack_h2(float a, float b) {
    __half2 h = __floats2half2_rn(a, b);
    return *(uint32_t*)&h;
}

// ---------------------------------------------------------------------------
// fp32 -> fp16 convert
// ---------------------------------------------------------------------------
__global__ void f2h_kernel(const float4* __restrict__ in, uint2* __restrict__ out, int n4) {
    int i = blockIdx.x * 256 + threadIdx.x;
    if (i < n4) {
        float4 v = in[i];
        out[i] = make_uint2(pack_h2(v.x, v.y), pack_h2(v.z, v.w));
    }
}

// fp32 W[K,N] -> fp16 WT[N,K]
__global__ void transpose_h(const float* __restrict__ W, __half* __restrict__ WT,
                            int K, int N) {
    __shared__ float tile[32][33];
    int n0 = blockIdx.x * 32, k0 = blockIdx.y * 32;
    int tx = threadIdx.x, ty = threadIdx.y;
#pragma unroll
    for (int i = 0; i < 4; i++)
        tile[ty + 8 * i][tx] = W[(size_t)(k0 + ty + 8 * i) * N + n0 + tx];
    __syncthreads();
#pragma unroll
    for (int i = 0; i < 4; i++)
        WT[(size_t)(n0 + ty + 8 * i) * K + k0 + tx] = __float2half(tile[tx][ty + 8 * i]);
}

// ---------------------------------------------------------------------------
// fp16 GEMM v3: C[M,N] = A[M,K] @ BT[N,K]^T + bias[N]
// Block 128x128, warp tile 64x32 (8 warps 2x4), BK=64, 2-stage cp.async.
// Smem A: [m][k] stride 72; B: [n][k] stride 72. 72KB/CTA -> 2 CTAs/SM.
// ---------------------------------------------------------------------------
#define BM 128
#define BN 128
#define GBK 64
#define GSTR 72                         // halves per row (64 + 8 pad)
#define ST_BYTES (128 * GSTR * 2)       // 18432 per matrix per stage
#define B_BASE   (2 * ST_BYTES)
#define SMEM_GEMM (4 * ST_BYTES)        // 73728

template<int WRITE_HALF>
__global__ __launch_bounds__(256, 2) void hgemm_v3(
    const __half* __restrict__ A, const __half* __restrict__ BT,
    const float* __restrict__ bias, void* __restrict__ Cout,
    int M, int N, int K)
{
    extern __shared__ __align__(16) char sm[];
    const uint32_t smb = smem_u32(sm);

    const int tid  = threadIdx.x;
    const int w    = tid >> 5;
    const int lane = tid & 31;
    const int g    = lane >> 2;
    const int tig  = lane & 3;
    const int brow = blockIdx.x * BM;
    const int bcol = blockIdx.y * BN;
    const int wr   = (w >> 2) * 64;    // warp m base: 0 / 64
    const int wc   = (w & 3) * 32;     // warp n base: 0..96

    // ldmatrix per-thread offsets (bytes)
    const uint32_t a_off = 2 * ((wr + (lane & 15)) * GSTR + (lane >> 4) * 8);
    const uint32_t b_off = 2 * ((wc + (lane & 15)) * GSTR + (lane >> 4) * 8);

    float acc[4][4][4];
#pragma unroll
    for (int i = 0; i < 4; i++)
#pragma unroll
        for (int j = 0; j < 4; j++)
#pragma unroll
            for (int f = 0; f < 4; f++) acc[i][j][f] = 0.f;

    auto load_chunk = [&](int s, int k0) {
#pragma unroll
        for (int l = 0; l < 4; l++) {          // A: 128 rows x 8 chunks of 8
            int idx = tid + l * 256;
            int m = idx >> 3, c = idx & 7;
            cp16(smb + s * ST_BYTES + 2 * (m * GSTR + c * 8),
                 A + (size_t)(brow + m) * K + k0 + c * 8);
        }
#pragma unroll
        for (int l = 0; l < 4; l++) {          // B: 128 rows x 8 chunks of 8
            int idx = tid + l * 256;
            int n = idx >> 3, c = idx & 7;
            cp16(smb + B_BASE + s * ST_BYTES + 2 * (n * GSTR + c * 8),
                 BT + (size_t)(bcol + n) * K + k0 + c * 8);
        }
        CP_COMMIT();
    };

    const int KT = K / GBK;     // 16
    load_chunk(0, 0);

    for (int t = 0; t < KT; t++) {
        const int cur = t & 1;
        if (t + 1 < KT) {
            load_chunk(cur ^ 1, (t + 1) * GBK);
            CP_WAIT(1);
        } else {
            CP_WAIT(0);
        }
        __syncthreads();

        const uint32_t as_s = smb + cur * ST_BYTES;
        const uint32_t bs_s = smb + B_BASE + cur * ST_BYTES;
#pragma unroll
        for (int ks = 0; ks < 64; ks += 16) {
            uint32_t af[4][4];
#pragma unroll
            for (int i = 0; i < 4; i++)
                LDSM_X4(af[i][0], af[i][1], af[i][2], af[i][3],
                        as_s + a_off + 2 * (i * 16 * GSTR + ks));
            uint32_t bf[4][2];
#pragma unroll
            for (int jp = 0; jp < 2; jp++) {
                uint32_t t0, t1, t2, t3;
                LDSM_X4(t0, t1, t2, t3,
                        bs_s + b_off + 2 * (jp * 16 * GSTR + ks));
                bf[2*jp][0]   = t0; bf[2*jp][1]   = t2;
                bf[2*jp+1][0] = t1; bf[2*jp+1][1] = t3;
            }
#pragma unroll
            for (int i = 0; i < 4; i++)
#pragma unroll
                for (int j = 0; j < 4; j++)
                    mma_f16(acc[i][j][0], acc[i][j][1], acc[i][j][2], acc[i][j][3],
                            af[i][0], af[i][1], af[i][2], af[i][3],
                            bf[j][0], bf[j][1]);
        }
        __syncthreads();
    }

    // Epilogue
#pragma unroll
    for (int i = 0; i < 4; i++) {
#pragma unroll
        for (int j = 0; j < 4; j++) {
            int row = brow + wr + i * 16 + g;
            int col = bcol + wc + j * 8 + 2 * tig;
            float b0 = bias[col], b1 = bias[col + 1];
            if (WRITE_HALF) {
                __half* Ch = (__half*)Cout;
                *(uint32_t*)&Ch[(size_t)row * N + col] =
                    pack_h2(acc[i][j][0] + b0, acc[i][j][1] + b1);
                *(uint32_t*)&Ch[(size_t)(row + 8) * N + col] =
                    pack_h2(acc[i][j][2] + b0, acc[i][j][3] + b1);
            } else {
                float* Cf = (float*)Cout;
                *(float2*)&Cf[(size_t)row * N + col] =
                    make_float2(acc[i][j][0] + b0, acc[i][j][1] + b1);
                *(float2*)&Cf[(size_t)(row + 8) * N + col] =
                    make_float2(acc[i][j][2] + b0, acc[i][j][3] + b1);
            }
        }
    }
}

// ---------------------------------------------------------------------------
// Causal flash attention, fp16 HMMA + ldmatrix, cp.async double-buffered K/V.
// Grid (T/128, H, B), 256 threads (8 warps x 16 q-rows = BQ 128), BKV=64.
// ---------------------------------------------------------------------------
#define QVSTR 72
#define Q_BYTES  (128 * QVSTR * 2)   // 18432
#define KV_BYTES (64 * QVSTR * 2)    // 9216
#define SM_K     Q_BYTES
#define SM_V     (SM_K + 2 * KV_BYTES)
#define SMEM_ATT (SM_V + 2 * KV_BYTES)   // 55296

__global__ __launch_bounds__(256) void attn_h_kernel(
    const __half* __restrict__ qkv, __half* __restrict__ y)
{
    extern __shared__ __align__(16) char sma[];
    const uint32_t qs_u = smem_u32(sma);
    const uint32_t ks_u = qs_u + SM_K;
    const uint32_t vs_u = qs_u + SM_V;
    __half* Qs = (__half*)sma;

    const int qb = blockIdx.x;
    const int h  = blockIdx.y;
    const int b  = blockIdx.z;
    const int tid  = threadIdx.x;
    const int w    = tid >> 5;
    const int lane = tid & 31;
    const int g    = lane >> 2;
    const int tig  = lane & 3;

    const uint32_t qa_off = 2 * ((w * 16 + (lane & 15)) * QVSTR + (lane >> 4) * 8);
    const uint32_t kb_off = 2 * (((lane & 7) + ((lane >> 4) ? 8 : 0)) * QVSTR + ((lane & 8) ? 8 : 0));
    const uint32_t vb_off = 2 * (((lane & 7) + (lane & 8)) * QVSTR + ((lane >> 4) ? 8 : 0));

    const __half* base = qkv + (size_t)(b * SEQ) * QKVN + h * HDIM;
    const int q0 = qb * 128;

    auto load_kv = [&](int s, int kt) {
#pragma unroll
        for (int l = 0; l < 2; l++) {
            int idx = tid + l * 256;
            int r = idx >> 3, c8 = (idx & 7) * 8;
            size_t ro = (size_t)(kt * 64 + r) * QKVN + c8;
            uint32_t so = s * KV_BYTES + 2 * (r * QVSTR + c8);
            cp16(ks_u + so, base + CDIM + ro);
            cp16(vs_u + so, base + 2 * CDIM + ro);
        }
        CP_COMMIT();
    };

    // Load Q tile (scaled by 1/8 = 1/sqrt(64); exact in fp16)
    const __half2 sc = __floats2half2_rn(0.125f, 0.125f);
#pragma unroll
    for (int l = 0; l < 4; l++) {
        int idx = tid + l * 256;
        int r = idx >> 3, c8 = (idx & 7) * 8;
        uint4 v = *(const uint4*)&base[(size_t)(q0 + r) * QKVN + c8];
        __half2* hv = (__half2*)&v;
        hv[0] = __hmul2(hv[0], sc); hv[1] = __hmul2(hv[1], sc);
        hv[2] = __hmul2(hv[2], sc); hv[3] = __hmul2(hv[3], sc);
        *(uint4*)&Qs[r * QVSTR + c8] = v;
    }

    float o[8][4];
#pragma unroll
    for (int j = 0; j < 8; j++)
#pragma unroll
        for (int f = 0; f < 4; f++) o[j][f] = 0.f;
    float m0 = -1e30f, m1 = -1e30f, l0 = 0.f, l1 = 0.f;

    const int last = 2 * qb + 1;
    load_kv(0, 0);

    for (int kt = 0; kt <= last; kt++) {
        const int bs = kt & 1;
        __syncthreads();
        if (kt < last) { load_kv(bs ^ 1, kt + 1); CP_WAIT(1); }
        else           { CP_WAIT(0); }
        __syncthreads();

        const uint32_t ksb = ks_u + bs * KV_BYTES;
        const uint32_t vsb = vs_u + bs * KV_BYTES;

        // S = Q K^T (warp rows 16, cols 64)
        float s[8][4];
#pragma unroll
        for (int j = 0; j < 8; j++)
#pragma unroll
            for (int f = 0; f < 4; f++) s[j][f] = 0.f;
#pragma unroll
        for (int ks = 0; ks < 64; ks += 16) {
            uint32_t a0, a1, a2, a3;
            LDSM_X4(a0, a1, a2, a3, qs_u + qa_off + 2 * ks);
#pragma unroll
            for (int jp = 0; jp < 4; jp++) {
                uint32_t b0, b1, b2, b3;
                LDSM_X4(b0, b1, b2, b3, ksb + kb_off + 2 * (jp * 16 * QVSTR + ks));
                mma_f16(s[2*jp][0], s[2*jp][1], s[2*jp][2], s[2*jp][3],
                        a0, a1, a2, a3, b0, b1);
                mma_f16(s[2*jp+1][0], s[2*jp+1][1], s[2*jp+1][2], s[2*jp+1][3],
                        a0, a1, a2, a3, b2, b3);
            }
        }

        // Causal mask (only tiles reaching this warp's diagonal need it)
        const int rl0 = q0 + w * 16 + g;
        if (kt * 64 + 63 > rl0) {
            const int r1g = rl0 + 8;
#pragma unroll
            for (int j = 0; j < 8; j++) {
                int c = kt * 64 + j * 8 + 2 * tig;
                if (c     > rl0) s[j][0] = -1e30f;
                if (c + 1 > rl0) s[j][1] = -1e30f;
                if (c     > r1g) s[j][2] = -1e30f;
                if (c + 1 > r1g) s[j][3] = -1e30f;
            }
        }

        // Online softmax
        float rm0 = -1e30f, rm1 = -1e30f;
#pragma unroll
        for (int j = 0; j < 8; j++) {
            rm0 = fmaxf(rm0, fmaxf(s[j][0], s[j][1]));
            rm1 = fmaxf(rm1, fmaxf(s[j][2], s[j][3]));
        }
#pragma unroll
        for (int off = 1; off < 4; off <<= 1) {
            rm0 = fmaxf(rm0, __shfl_xor_sync(0xffffffffu, rm0, off));
            rm1 = fmaxf(rm1, __shfl_xor_sync(0xffffffffu, rm1, off));
        }
        float mn0 = fmaxf(m0, rm0), mn1 = fmaxf(m1, rm1);
        float al0 = __expf(m0 - mn0), al1 = __expf(m1 - mn1);
        float ls0 = 0.f, ls1 = 0.f;
#pragma unroll
        for (int j = 0; j < 8; j++) {
            s[j][0] = __expf(s[j][0] - mn0);
            s[j][1] = __expf(s[j][1] - mn0);
            s[j][2] = __expf(s[j][2] - mn1);
            s[j][3] = __expf(s[j][3] - mn1);
            ls0 += s[j][0] + s[j][1];
            ls1 += s[j][2] + s[j][3];
        }
#pragma unroll
        for (int off = 1; off < 4; off <<= 1) {
            ls0 += __shfl_xor_sync(0xffffffffu, ls0, off);
            ls1 += __shfl_xor_sync(0xffffffffu, ls1, off);
        }
        l0 = l0 * al0 + ls0;
        l1 = l1 * al1 + ls1;
        m0 = mn0; m1 = mn1;
#pragma unroll
        for (int j = 0; j < 8; j++) {
            o[j][0] *= al0; o[j][1] *= al0;
            o[j][2] *= al1; o[j][3] *= al1;
        }

        // O += P @ V
#pragma unroll
        for (int ks2 = 0; ks2 < 4; ks2++) {
            uint32_t a0 = pack_h2(s[2*ks2][0],   s[2*ks2][1]);
            uint32_t a1 = pack_h2(s[2*ks2][2],   s[2*ks2][3]);
            uint32_t a2 = pack_h2(s[2*ks2+1][0], s[2*ks2+1][1]);
            uint32_t a3 = pack_h2(s[2*ks2+1][2], s[2*ks2+1][3]);
#pragma unroll
            for (int jp = 0; jp < 4; jp++) {
                uint32_t b0, b1, b2, b3;
                LDSM_X4_T(b0, b1, b2, b3,
                          vsb + vb_off + 2 * (ks2 * 16 * QVSTR + jp * 16));
                mma_f16(o[2*jp][0], o[2*jp][1], o[2*jp][2], o[2*jp][3],
                        a0, a1, a2, a3, b0, b1);
                mma_f16(o[2*jp+1][0], o[2*jp+1][1], o[2*jp+1][2], o[2*jp+1][3],
                        a0, a1, a2, a3, b2, b3);
            }
        }
    }

    float il0 = 1.0f / l0, il1 = 1.0f / l1;
    size_t r0 = (size_t)(b * SEQ + q0 + w * 16 + g) * CDIM + h * HDIM;
    size_t r1 = r0 + 8 * CDIM;
#pragma unroll
    for (int j = 0; j < 8; j++) {
        int c = j * 8 + 2 * tig;
        *(uint32_t*)&y[r0 + c] = pack_h2(o[j][0] * il0, o[j][1] * il0);
        *(uint32_t*)&y[r1 + c] = pack_h2(o[j][2] * il1, o[j][3] * il1);
    }
}

// ---------------------------------------------------------------------------
extern "C" void kernel_launch(void* const* d_in, const int* in_sizes, int n_in,
                              void* d_out, int out_size)
{
    const float* x      = (const float*)d_in[0];
    const float* W_attn = (const float*)d_in[1];
    const float* b_attn = (const float*)d_in[2];
    const float* W_proj = (const float*)d_in[3];
    const float* b_proj = (const float*)d_in[4];
    float* out = (float*)d_out;

    __half *xh, *wat, *wpt, *qkvh, *yh;
    cudaGetSymbolAddress((void**)&xh,   g_xh);
    cudaGetSymbolAddress((void**)&wat,  g_wat);
    cudaGetSymbolAddress((void**)&wpt,  g_wpt);
    cudaGetSymbolAddress((void**)&qkvh, g_qkvh);
    cudaGetSymbolAddress((void**)&yh,   g_yh);

    cudaFuncSetAttribute(hgemm_v3<1>, cudaFuncAttributeMaxDynamicSharedMemorySize, SMEM_GEMM);
    cudaFuncSetAttribute(hgemm_v3<0>, cudaFuncAttributeMaxDynamicSharedMemorySize, SMEM_GEMM);
    cudaFuncSetAttribute(attn_h_kernel, cudaFuncAttributeMaxDynamicSharedMemorySize, SMEM_ATT);

    // 0) fp16 conversions / weight transposes
    {
        int n4 = (MROWS * CDIM) / 4;
        f2h_kernel<<<(n4 + 255) / 256, 256>>>((const float4*)x, (uint2*)xh, n4);
        transpose_h<<<dim3(QKVN / 32, CDIM / 32), dim3(32, 8)>>>(W_attn, wat, CDIM, QKVN);
        transpose_h<<<dim3(CDIM / 32, CDIM / 32), dim3(32, 8)>>>(W_proj, wpt, CDIM, CDIM);
    }
    // 1) QKV projection (fp16 out)
    {
        dim3 grid(MROWS / BM, QKVN / BN);
        hgemm_v3<1><<<grid, 256, SMEM_GEMM>>>(xh, wat, b_attn, qkvh, MROWS, QKVN, CDIM);
    }
    // 2) Causal attention (fp16 out)
    {
        dim3 grid(SEQ / 128, NHEAD, BATCH);
        attn_h_kernel<<<grid, 256, SMEM_ATT>>>(qkvh, yh);
    }
    // 3) Output projection (fp32 out)
    {
        dim3 grid(MROWS / BM, CDIM / BN);
        hgemm_v3<0><<<grid, 256, SMEM_GEMM>>>(yh, wpt, b_proj, out, MROWS, CDIM, CDIM);
    }
}

// round 8
// speedup vs baseline: 1.1754x; 1.0238x over previous
#include <cuda_runtime.h>
#include <cuda_fp16.h>
#include <cstdint>

// Problem constants
#define BATCH 4
#define SEQ   2048
#define CDIM  1024
#define NHEAD 16
#define HDIM  64
#define MROWS (BATCH*SEQ)          // 8192
#define QKVN  (3*CDIM)             // 3072

// fp16 scratch
__device__ __half g_xh  [(size_t)MROWS * CDIM];
__device__ __half g_wat [(size_t)QKVN * CDIM];   // W_attn^T [N,K]
__device__ __half g_wpt [(size_t)CDIM * CDIM];   // W_proj^T [N,K]
__device__ __half g_qkvh[(size_t)MROWS * QKVN];
__device__ __half g_yh  [(size_t)MROWS * CDIM];

// ---------------------------------------------------------------------------
__device__ __forceinline__ uint32_t smem_u32(const void* p) {
    uint32_t a;
    asm("{ .reg .u64 t; cvta.to.shared.u64 t, %1; cvt.u32.u64 %0, t; }" : "=r"(a) : "l"(p));
    return a;
}
__device__ __forceinline__ void cp16(uint32_t s, const void* g) {
    asm volatile("cp.async.cg.shared.global [%0], [%1], 16;" :: "r"(s), "l"(g));
}
#define CP_COMMIT() asm volatile("cp.async.commit_group;")
#define CP_WAIT(n)  asm volatile("cp.async.wait_group %0;" :: "n"(n))

#define LDSM_X4(r0,r1,r2,r3,addr) \
    asm volatile("ldmatrix.sync.aligned.m8n8.x4.shared.b16 {%0,%1,%2,%3},[%4];" \
        : "=r"(r0),"=r"(r1),"=r"(r2),"=r"(r3) : "r"(addr))
#define LDSM_X4_T(r0,r1,r2,r3,addr) \
    asm volatile("ldmatrix.sync.aligned.m8n8.x4.trans.shared.b16 {%0,%1,%2,%3},[%4];" \
        : "=r"(r0),"=r"(r1),"=r"(r2),"=r"(r3) : "r"(addr))

__device__ __forceinline__ void mma_f16(
    float& c0, float& c1, float& c2, float& c3,
    uint32_t a0, uint32_t a1, uint32_t a2, uint32_t a3,
    uint32_t b0, uint32_t b1)
{
    asm volatile(
        "mma.sync.aligned.m16n8k16.row.col.f32.f16.f16.f32 "
        "{%0,%1,%2,%3}, {%4,%5,%6,%7}, {%8,%9}, {%0,%1,%2,%3};"
        : "+f"(c0), "+f"(c1), "+f"(c2), "+f"(c3)
        : "r"(a0), "r"(a1), "r"(a2), "r"(a3), "r"(b0), "r"(b1));
}
__device__ __forceinline__ uint32_t pack_h2(float a, float b) {
    __half2 h = __floats2half2_rn(a, b);
    return *(uint32_t*)&h;
}

// ---------------------------------------------------------------------------
// fp32 -> fp16 convert
// ---------------------------------------------------------------------------
__global__ void f2h_kernel(const float4* __restrict__ in, uint2* __restrict__ out, int n4) {
    int i = blockIdx.x * 256 + threadIdx.x;
    if (i < n4) {
        float4 v = in[i];
        out[i] = make_uint2(pack_h2(v.x, v.y), pack_h2(v.z, v.w));
    }
}

// fp32 W[K,N] -> fp16 WT[N,K]
__global__ void transpose_h(const float* __restrict__ W, __half* __restrict__ WT,
                            int K, int N) {
    __shared__ float tile[32][33];
    int n0 = blockIdx.x * 32, k0 = blockIdx.y * 32;
    int tx = threadIdx.x, ty = threadIdx.y;
#pragma unroll
    for (int i = 0; i < 4; i++)
        tile[ty + 8 * i][tx] = W[(size_t)(k0 + ty + 8 * i) * N + n0 + tx];
    __syncthreads();
#pragma unroll
    for (int i = 0; i < 4; i++)
        WT[(size_t)(n0 + ty + 8 * i) * K + k0 + tx] = __float2half(tile[tx][ty + 8 * i]);
}

// ---------------------------------------------------------------------------
// fp16 GEMM v4: C[M,N] = A[M,K] @ BT[N,K]^T + bias[N]
// Block 128x128, warp tile 64x32 (8 warps 2x4), BK=64, 3-stage cp.async ring,
// ONE __syncthreads per K-iteration.
// ---------------------------------------------------------------------------
#define BM 128
#define BN 128
#define GBK 64
#define GSTR 72                          // halves per row (64 + 8 pad)
#define STG_A     (128 * GSTR * 2)       // 18432 (A part of a stage)
#define STG_BYTES (2 * STG_A)            // 36864 (A + B)
#define SMEM_GEMM (3 * STG_BYTES)        // 110592

template<int WRITE_HALF>
__global__ __launch_bounds__(256, 2) void hgemm_v4(
    const __half* __restrict__ A, const __half* __restrict__ BT,
    const float* __restrict__ bias, void* __restrict__ Cout,
    int M, int N, int K)
{
    extern __shared__ __align__(16) char sm[];
    const uint32_t smb = smem_u32(sm);

    const int tid  = threadIdx.x;
    const int w    = tid >> 5;
    const int lane = tid & 31;
    const int g    = lane >> 2;
    const int tig  = lane & 3;
    const int brow = blockIdx.x * BM;
    const int bcol = blockIdx.y * BN;
    const int wr   = (w >> 2) * 64;    // warp m base: 0 / 64
    const int wc   = (w & 3) * 32;     // warp n base: 0..96

    const uint32_t a_off = 2 * ((wr + (lane & 15)) * GSTR + (lane >> 4) * 8);
    const uint32_t b_off = 2 * ((wc + (lane & 15)) * GSTR + (lane >> 4) * 8);

    float acc[4][4][4];
#pragma unroll
    for (int i = 0; i < 4; i++)
#pragma unroll
        for (int j = 0; j < 4; j++)
#pragma unroll
            for (int f = 0; f < 4; f++) acc[i][j][f] = 0.f;

    auto load_chunk = [&](int s, int k0) {
        const uint32_t ab = smb + s * STG_BYTES;
        const uint32_t bb = ab + STG_A;
#pragma unroll
        for (int l = 0; l < 4; l++) {          // A: 128 rows x 8 chunks of 8
            int idx = tid + l * 256;
            int m = idx >> 3, c = idx & 7;
            cp16(ab + 2 * (m * GSTR + c * 8),
                 A + (size_t)(brow + m) * K + k0 + c * 8);
        }
#pragma unroll
        for (int l = 0; l < 4; l++) {          // B: 128 rows x 8 chunks of 8
            int idx = tid + l * 256;
            int n = idx >> 3, c = idx & 7;
            cp16(bb + 2 * (n * GSTR + c * 8),
                 BT + (size_t)(bcol + n) * K + k0 + c * 8);
        }
        CP_COMMIT();
    };

    const int KT = K / GBK;     // 16
    load_chunk(0, 0);
    load_chunk(1, GBK);

    for (int t = 0; t < KT; t++) {
        const int cur = t % 3;
        if (t == KT - 1) { CP_WAIT(0); } else { CP_WAIT(1); }
        __syncthreads();
        if (t + 2 < KT) load_chunk((t + 2) % 3, (t + 2) * GBK);

        const uint32_t as_s = smb + cur * STG_BYTES;
        const uint32_t bs_s = as_s + STG_A;
#pragma unroll
        for (int ks = 0; ks < 64; ks += 16) {
            uint32_t af[4][4];
#pragma unroll
            for (int i = 0; i < 4; i++)
                LDSM_X4(af[i][0], af[i][1], af[i][2], af[i][3],
                        as_s + a_off + 2 * (i * 16 * GSTR + ks));
            uint32_t bf[4][2];
#pragma unroll
            for (int jp = 0; jp < 2; jp++) {
                uint32_t t0, t1, t2, t3;
                LDSM_X4(t0, t1, t2, t3,
                        bs_s + b_off + 2 * (jp * 16 * GSTR + ks));
                bf[2*jp][0]   = t0; bf[2*jp][1]   = t2;
                bf[2*jp+1][0] = t1; bf[2*jp+1][1] = t3;
            }
#pragma unroll
            for (int i = 0; i < 4; i++)
#pragma unroll
                for (int j = 0; j < 4; j++)
                    mma_f16(acc[i][j][0], acc[i][j][1], acc[i][j][2], acc[i][j][3],
                            af[i][0], af[i][1], af[i][2], af[i][3],
                            bf[j][0], bf[j][1]);
        }
    }

    // Epilogue
#pragma unroll
    for (int i = 0; i < 4; i++) {
#pragma unroll
        for (int j = 0; j < 4; j++) {
            int row = brow + wr + i * 16 + g;
            int col = bcol + wc + j * 8 + 2 * tig;
            float b0 = bias[col], b1 = bias[col + 1];
            if (WRITE_HALF) {
                __half* Ch = (__half*)Cout;
                *(uint32_t*)&Ch[(size_t)row * N + col] =
                    pack_h2(acc[i][j][0] + b0, acc[i][j][1] + b1);
                *(uint32_t*)&Ch[(size_t)(row + 8) * N + col] =
                    pack_h2(acc[i][j][2] + b0, acc[i][j][3] + b1);
            } else {
                float* Cf = (float*)Cout;
                *(float2*)&Cf[(size_t)row * N + col] =
                    make_float2(acc[i][j][0] + b0, acc[i][j][1] + b1);
                *(float2*)&Cf[(size_t)(row + 8) * N + col] =
                    make_float2(acc[i][j][2] + b0, acc[i][j][3] + b1);
            }
        }
    }
}

// ---------------------------------------------------------------------------
// Causal flash attention, fp16 HMMA + ldmatrix, 3-stage cp.async KV ring,
// ONE __syncthreads per KV tile. Grid (T/128, H, B), 256 threads, BQ=128, BKV=64.
// Heavy tiles launched first (qb reversed).
// ---------------------------------------------------------------------------
#define QVSTR 72
#define Q_BYTES  (128 * QVSTR * 2)   // 18432
#define KV_BYTES (64 * QVSTR * 2)    // 9216
#define SM_K     Q_BYTES
#define SM_V     (SM_K + 3 * KV_BYTES)
#define SMEM_ATT (SM_V + 3 * KV_BYTES)   // 73728

__global__ __launch_bounds__(256) void attn_h_kernel(
    const __half* __restrict__ qkv, __half* __restrict__ y)
{
    extern __shared__ __align__(16) char sma[];
    const uint32_t qs_u = smem_u32(sma);
    const uint32_t ks_u = qs_u + SM_K;
    const uint32_t vs_u = qs_u + SM_V;
    __half* Qs = (__half*)sma;

    const int qb = (gridDim.x - 1) - blockIdx.x;   // heavy tiles first
    const int h  = blockIdx.y;
    const int b  = blockIdx.z;
    const int tid  = threadIdx.x;
    const int w    = tid >> 5;
    const int lane = tid & 31;
    const int g    = lane >> 2;
    const int tig  = lane & 3;

    const uint32_t qa_off = 2 * ((w * 16 + (lane & 15)) * QVSTR + (lane >> 4) * 8);
    const uint32_t kb_off = 2 * (((lane & 7) + ((lane >> 4) ? 8 : 0)) * QVSTR + ((lane & 8) ? 8 : 0));
    const uint32_t vb_off = 2 * (((lane & 7) + (lane & 8)) * QVSTR + ((lane >> 4) ? 8 : 0));

    const __half* base = qkv + (size_t)(b * SEQ) * QKVN + h * HDIM;
    const int q0 = qb * 128;

    auto load_kv = [&](int s, int kt) {
#pragma unroll
        for (int l = 0; l < 2; l++) {
            int idx = tid + l * 256;
            int r = idx >> 3, c8 = (idx & 7) * 8;
            size_t ro = (size_t)(kt * 64 + r) * QKVN + c8;
            uint32_t so = s * KV_BYTES + 2 * (r * QVSTR + c8);
            cp16(ks_u + so, base + CDIM + ro);
            cp16(vs_u + so, base + 2 * CDIM + ro);
        }
        CP_COMMIT();
    };

    // Load Q tile (scaled by 1/8 = 1/sqrt(64); exact in fp16)
    const __half2 sc = __floats2half2_rn(0.125f, 0.125f);
#pragma unroll
    for (int l = 0; l < 4; l++) {
        int idx = tid + l * 256;
        int r = idx >> 3, c8 = (idx & 7) * 8;
        uint4 v = *(const uint4*)&base[(size_t)(q0 + r) * QKVN + c8];
        __half2* hv = (__half2*)&v;
        hv[0] = __hmul2(hv[0], sc); hv[1] = __hmul2(hv[1], sc);
        hv[2] = __hmul2(hv[2], sc); hv[3] = __hmul2(hv[3], sc);
        *(uint4*)&Qs[r * QVSTR + c8] = v;
    }

    float o[8][4];
#pragma unroll
    for (int j = 0; j < 8; j++)
#pragma unroll
        for (int f = 0; f < 4; f++) o[j][f] = 0.f;
    float m0 = -1e30f, m1 = -1e30f, l0 = 0.f, l1 = 0.f;

    const int last = 2 * qb + 1;        // >= 1 always
    load_kv(0, 0);
    load_kv(1, 1);

    for (int kt = 0; kt <= last; kt++) {
        const int cur = kt % 3;
        if (kt == last) { CP_WAIT(0); } else { CP_WAIT(1); }
        __syncthreads();
        if (kt + 2 <= last) load_kv((kt + 2) % 3, kt + 2);

        const uint32_t ksb = ks_u + cur * KV_BYTES;
        const uint32_t vsb = vs_u + cur * KV_BYTES;

        // S = Q K^T (warp rows 16, cols 64)
        float s[8][4];
#pragma unroll
        for (int j = 0; j < 8; j++)
#pragma unroll
            for (int f = 0; f < 4; f++) s[j][f] = 0.f;
#pragma unroll
        for (int ks = 0; ks < 64; ks += 16) {
            uint32_t a0, a1, a2, a3;
            LDSM_X4(a0, a1, a2, a3, qs_u + qa_off + 2 * ks);
#pragma unroll
            for (int jp = 0; jp < 4; jp++) {
                uint32_t b0, b1, b2, b3;
                LDSM_X4(b0, b1, b2, b3, ksb + kb_off + 2 * (jp * 16 * QVSTR + ks));
                mma_f16(s[2*jp][0], s[2*jp][1], s[2*jp][2], s[2*jp][3],
                        a0, a1, a2, a3, b0, b1);
                mma_f16(s[2*jp+1][0], s[2*jp+1][1], s[2*jp+1][2], s[2*jp+1][3],
                        a0, a1, a2, a3, b2, b3);
            }
        }

        // Causal mask (only tiles reaching this warp's diagonal need it)
        const int rl0 = q0 + w * 16 + g;
        if (kt * 64 + 63 > rl0) {
            const int r1g = rl0 + 8;
#pragma unroll
            for (int j = 0; j < 8; j++) {
                int c = kt * 64 + j * 8 + 2 * tig;
                if (c     > rl0) s[j][0] = -1e30f;
                if (c + 1 > rl0) s[j][1] = -1e30f;
                if (c     > r1g) s[j][2] = -1e30f;
                if (c + 1 > r1g) s[j][3] = -1e30f;
            }
        }

        // Online softmax
        float rm0 = -1e30f, rm1 = -1e30f;
#pragma unroll
        for (int j = 0; j < 8; j++) {
            rm0 = fmaxf(rm0, fmaxf(s[j][0], s[j][1]));
            rm1 = fmaxf(rm1, fmaxf(s[j][2], s[j][3]));
        }
#pragma unroll
        for (int off = 1; off < 4; off <<= 1) {
            rm0 = fmaxf(rm0, __shfl_xor_sync(0xffffffffu, rm0, off));
            rm1 = fmaxf(rm1, __shfl_xor_sync(0xffffffffu, rm1, off));
        }
        float mn0 = fmaxf(m0, rm0), mn1 = fmaxf(m1, rm1);
        float al0 = __expf(m0 - mn0), al1 = __expf(m1 - mn1);
        float ls0 = 0.f, ls1 = 0.f;
#pragma unroll
        for (int j = 0; j < 8; j++) {
            s[j][0] = __expf(s[j][0] - mn0);
            s[j][1] = __expf(s[j][1] - mn0);
            s[j][2] = __expf(s[j][2] - mn1);
            s[j][3] = __expf(s[j][3] - mn1);
            ls0 += s[j][0] + s[j][1];
            ls1 += s[j][2] + s[j][3];
        }
#pragma unroll
        for (int off = 1; off < 4; off <<= 1) {
            ls0 += __shfl_xor_sync(0xffffffffu, ls0, off);
            ls1 += __shfl_xor_sync(0xffffffffu, ls1, off);
        }
        l0 = l0 * al0 + ls0;
        l1 = l1 * al1 + ls1;
        m0 = mn0; m1 = mn1;
#pragma unroll
        for (int j = 0; j < 8; j++) {
            o[j][0] *= al0; o[j][1] *= al0;
            o[j][2] *= al1; o[j][3] *= al1;
        }

        // O += P @ V
#pragma unroll
        for (int ks2 = 0; ks2 < 4; ks2++) {
            uint32_t a0 = pack_h2(s[2*ks2][0],   s[2*ks2][1]);
            uint32_t a1 = pack_h2(s[2*ks2][2],   s[2*ks2][3]);
            uint32_t a2 = pack_h2(s[2*ks2+1][0], s[2*ks2+1][1]);
            uint32_t a3 = pack_h2(s[2*ks2+1][2], s[2*ks2+1][3]);
#pragma unroll
            for (int jp = 0; jp < 4; jp++) {
                uint32_t b0, b1, b2, b3;
                LDSM_X4_T(b0, b1, b2, b3,
                          vsb + vb_off + 2 * (ks2 * 16 * QVSTR + jp * 16));
                mma_f16(o[2*jp][0], o[2*jp][1], o[2*jp][2], o[2*jp][3],
                        a0, a1, a2, a3, b0, b1);
                mma_f16(o[2*jp+1][0], o[2*jp+1][1], o[2*jp+1][2], o[2*jp+1][3],
                        a0, a1, a2, a3, b2, b3);
            }
        }
    }

    float il0 = 1.0f / l0, il1 = 1.0f / l1;
    size_t r0 = (size_t)(b * SEQ + q0 + w * 16 + g) * CDIM + h * HDIM;
    size_t r1 = r0 + 8 * CDIM;
#pragma unroll
    for (int j = 0; j < 8; j++) {
        int c = j * 8 + 2 * tig;
        *(uint32_t*)&y[r0 + c] = pack_h2(o[j][0] * il0, o[j][1] * il0);
        *(uint32_t*)&y[r1 + c] = pack_h2(o[j][2] * il1, o[j][3] * il1);
    }
}

// ---------------------------------------------------------------------------
extern "C" void kernel_launch(void* const* d_in, const int* in_sizes, int n_in,
                              void* d_out, int out_size)
{
    const float* x      = (const float*)d_in[0];
    const float* W_attn = (const float*)d_in[1];
    const float* b_attn = (const float*)d_in[2];
    const float* W_proj = (const float*)d_in[3];
    const float* b_proj = (const float*)d_in[4];
    float* out = (float*)d_out;

    __half *xh, *wat, *wpt, *qkvh, *yh;
    cudaGetSymbolAddress((void**)&xh,   g_xh);
    cudaGetSymbolAddress((void**)&wat,  g_wat);
    cudaGetSymbolAddress((void**)&wpt,  g_wpt);
    cudaGetSymbolAddress((void**)&qkvh, g_qkvh);
    cudaGetSymbolAddress((void**)&yh,   g_yh);

    cudaFuncSetAttribute(hgemm_v4<1>, cudaFuncAttributeMaxDynamicSharedMemorySize, SMEM_GEMM);
    cudaFuncSetAttribute(hgemm_v4<0>, cudaFuncAttributeMaxDynamicSharedMemorySize, SMEM_GEMM);
    cudaFuncSetAttribute(attn_h_kernel, cudaFuncAttributeMaxDynamicSharedMemorySize, SMEM_ATT);

    // 0) fp16 conversions / weight transposes
    {
        int n4 = (MROWS * CDIM) / 4;
        f2h_kernel<<<(n4 + 255) / 256, 256>>>((const float4*)x, (uint2*)xh, n4);
        transpose_h<<<dim3(QKVN / 32, CDIM / 32), dim3(32, 8)>>>(W_attn, wat, CDIM, QKVN);
        transpose_h<<<dim3(CDIM / 32, CDIM / 32), dim3(32, 8)>>>(W_proj, wpt, CDIM, CDIM);
    }
    // 1) QKV projection (fp16 out)
    {
        dim3 grid(MROWS / BM, QKVN / BN);
        hgemm_v4<1><<<grid, 256, SMEM_GEMM>>>(xh, wat, b_attn, qkvh, MROWS, QKVN, CDIM);
    }
    // 2) Causal attention (fp16 out)
    {
        dim3 grid(SEQ / 128, NHEAD, BATCH);
        attn_h_kernel<<<grid, 256, SMEM_ATT>>>(qkvh, yh);
    }
    // 3) Output projection (fp32 out)
    {
        dim3 grid(MROWS / BM, CDIM / BN);
        hgemm_v4<0><<<grid, 256, SMEM_GEMM>>>(yh, wpt, b_proj, out, MROWS, CDIM, CDIM);
    }
}